// round 3
// baseline (speedup 1.0000x reference)
#include <cuda_runtime.h>
#include <cuda_fp16.h>
#include <cstdint>

#define NSTEPS 32

// ---- smem layout (bytes) ----
#define OFF_W1T 0        // 4 nets x 64 n-rows x 72 halves (pitch 72) = 36864
#define OFF_A   36864    // 2 nets x 128 rows x 68 halves (pitch 68)  = 34816
#define OFF_W04 71680    // float4[256]
#define OFF_BW  75776    // float2[256] (b1, w2)
#define OFF_B0  77824    // float[256]
#define OFF_F   78848    // float[2][128]
#define OFF_B2  79872    // float[4]
#define OFF_RED 79888    // float[4]
#define SMEM_BYTES 79936

#define A_NET_HALVES   8704   // 128*68
#define A_PITCH_W      34     // words per A row
#define B_NET_WORDS    2304   // 64*36
#define B_PITCH_W      36

__device__ float g_partial[256];

__device__ __forceinline__ float tanh_acc(float x) {
    float a = fabsf(x);
    float e = __expf(-2.0f * a);
    float t = __fdividef(1.0f - e, 1.0f + e);
    return copysignf(t, x);
}

__device__ __forceinline__ void mma16816(float& c0, float& c1, float& c2, float& c3,
                                         uint32_t a0, uint32_t a1, uint32_t a2, uint32_t a3,
                                         uint32_t b0, uint32_t b1) {
    asm volatile(
        "mma.sync.aligned.m16n8k16.row.col.f32.f16.f16.f32 "
        "{%0,%1,%2,%3},{%4,%5,%6,%7},{%8,%9},{%0,%1,%2,%3};"
        : "+f"(c0), "+f"(c1), "+f"(c2), "+f"(c3)
        : "r"(a0), "r"(a1), "r"(a2), "r"(a3), "r"(b0), "r"(b1));
}

// One phase: 2 MLPs (nets nb, nb+1) on shared input (S,V,rf,tcol) -> fA, fB per row.
// Entirely warp-local: each warp produces and consumes its own 32 rows.
__device__ __forceinline__ void run_phase(
    int nb, float S, float V, float rfv, float tcol,
    char* ab, int tid, int wid, int lane, float& fA, float& fB)
{
    const float4* w04 = (const float4*)(ab + OFF_W04);
    const float2* bw  = (const float2*)(ab + OFF_BW);
    const float*  b0s = (const float*)(ab + OFF_B0);
    const float*  b2s = (const float*)(ab + OFF_B2);
    uint32_t* Aw  = (uint32_t*)(ab + OFF_A);
    const uint32_t* Bw = (const uint32_t*)(ab + OFF_W1T);
    float* f_arr = (float*)(ab + OFF_F);

    const int g   = lane >> 2;   // group id (row within tiles)
    const int tig = lane & 3;    // thread in group
    const int wb  = wid * 32;    // warp's row base

    __syncwarp();   // WAR: prior phase's A/f reads done before overwrite

    // ---- layer 0: scalar fp32 -> h1 (fp16) into smem A, row = tid ----
    #pragma unroll
    for (int nl = 0; nl < 2; ++nl) {
        const int net = nb + nl;
        const float4* wp  = w04 + net * 64;
        const float*  b0p = b0s + net * 64;
        uint32_t* Arow = Aw + nl * (A_NET_HALVES / 2) + tid * A_PITCH_W;
        #pragma unroll 8
        for (int jj = 0; jj < 64; jj += 2) {
            float4 wa = wp[jj];
            float4 wbv = wp[jj + 1];
            float p0 = fmaf(wa.x, S, fmaf(wa.y, V, fmaf(wa.z, rfv, fmaf(wa.w, tcol, b0p[jj]))));
            float p1 = fmaf(wbv.x, S, fmaf(wbv.y, V, fmaf(wbv.z, rfv, fmaf(wbv.w, tcol, b0p[jj + 1]))));
            float h0 = tanh_acc(p0);
            float h1 = tanh_acc(p1);
            __half2 hh = __floats2half2_rn(h0, h1);
            Arow[jj >> 1] = *(const uint32_t*)&hh;
        }
    }
    __syncwarp();

    // ---- layer 1 (HMMA) + epilogue, per net ----
    #pragma unroll
    for (int nl = 0; nl < 2; ++nl) {
        const int net = nb + nl;

        // A fragments: 2 m-tiles x 4 k-tiles x 4 regs
        uint32_t afr[2][4][4];
        #pragma unroll
        for (int i = 0; i < 2; ++i) {
            const int row = wb + i * 16 + g;
            const uint32_t base = nl * (A_NET_HALVES / 2) + row * A_PITCH_W + tig;
            #pragma unroll
            for (int kt = 0; kt < 4; ++kt) {
                const uint32_t w = base + kt * 8;
                afr[i][kt][0] = Aw[w];
                afr[i][kt][1] = Aw[w + 8 * A_PITCH_W];
                afr[i][kt][2] = Aw[w + 4];
                afr[i][kt][3] = Aw[w + 4 + 8 * A_PITCH_W];
            }
        }

        float partial[4] = {0.f, 0.f, 0.f, 0.f};
        const uint32_t bbase = net * B_NET_WORDS + tig;

        #pragma unroll
        for (int j = 0; j < 8; ++j) {
            // B fragments for this n-tile (col n = j*8+g), all 4 k-tiles
            uint32_t bfr[4][2];
            const uint32_t bj = bbase + (j * 8 + g) * B_PITCH_W;
            #pragma unroll
            for (int kt = 0; kt < 4; ++kt) {
                bfr[kt][0] = Bw[bj + kt * 8];
                bfr[kt][1] = Bw[bj + kt * 8 + 4];
            }
            float c[2][4] = {{0.f,0.f,0.f,0.f},{0.f,0.f,0.f,0.f}};
            #pragma unroll
            for (int kt = 0; kt < 4; ++kt) {
                #pragma unroll
                for (int i = 0; i < 2; ++i)
                    mma16816(c[i][0], c[i][1], c[i][2], c[i][3],
                             afr[i][kt][0], afr[i][kt][1], afr[i][kt][2], afr[i][kt][3],
                             bfr[kt][0], bfr[kt][1]);
            }
            // epilogue for this n-tile: h2 = tanh(c + b1[n]); partial += h2*w2[n]
            const int n0 = j * 8 + tig * 2;
            float2 bw0 = bw[net * 64 + n0];
            float2 bw1 = bw[net * 64 + n0 + 1];
            #pragma unroll
            for (int i = 0; i < 2; ++i) {
                float h00 = tanh_acc(c[i][0] + bw0.x);
                float h01 = tanh_acc(c[i][1] + bw1.x);
                float h10 = tanh_acc(c[i][2] + bw0.x);
                float h11 = tanh_acc(c[i][3] + bw1.x);
                partial[2 * i]     = fmaf(h00, bw0.y, fmaf(h01, bw1.y, partial[2 * i]));
                partial[2 * i + 1] = fmaf(h10, bw0.y, fmaf(h11, bw1.y, partial[2 * i + 1]));
            }
        }
        // reduce across the 4 lanes of each g-group
        #pragma unroll
        for (int r = 0; r < 4; ++r) {
            partial[r] += __shfl_xor_sync(0xFFFFFFFFu, partial[r], 1);
            partial[r] += __shfl_xor_sync(0xFFFFFFFFu, partial[r], 2);
        }
        if (tig == 0) {
            const float bb = b2s[net];
            f_arr[nl * 128 + wb + g]      = partial[0] + bb;
            f_arr[nl * 128 + wb + g + 8]  = partial[1] + bb;
            f_arr[nl * 128 + wb + g + 16] = partial[2] + bb;
            f_arr[nl * 128 + wb + g + 24] = partial[3] + bb;
        }
    }
    __syncwarp();
    fA = f_arr[tid];
    fB = f_arr[128 + tid];
}

__global__ void __launch_bounds__(128)
nsde_main_kernel(const float* __restrict__ S0g, const float* __restrict__ Kg,
                 const float* __restrict__ Tg,  const float* __restrict__ rfg,
                 const float* __restrict__ Z1g, const float* __restrict__ Z2g,
                 const float* __restrict__ W0g, const float* __restrict__ b0g,
                 const float* __restrict__ W1g, const float* __restrict__ b1g,
                 const float* __restrict__ W2g, const float* __restrict__ b2g)
{
    extern __shared__ char ab[];
    const int tid  = threadIdx.x;
    const int wid  = tid >> 5;
    const int lane = tid & 31;
    const int b    = blockIdx.x & 63;   // option
    const int pb   = blockIdx.x >> 6;   // path block

    // ---- stage W1^T as fp16 [net][n][k], pitch 72 halves ----
    __half* W1T = (__half*)(ab + OFF_W1T);
    for (int i = tid; i < 4 * 64 * 64; i += 128) {
        const int net = i >> 12;
        const int k   = (i >> 6) & 63;
        const int n   = i & 63;
        W1T[net * 4608 + n * 72 + k] = __float2half_rn(W1g[i]);
    }
    float4* w04 = (float4*)(ab + OFF_W04);
    float2* bw  = (float2*)(ab + OFF_BW);
    float*  b0s = (float*)(ab + OFF_B0);
    float*  b2s = (float*)(ab + OFF_B2);
    float*  red = (float*)(ab + OFF_RED);
    for (int i = tid; i < 256; i += 128) {
        const int net = i >> 6, jj = i & 63;
        float4 v;
        v.x = W0g[net * 256 + 0 * 64 + jj];
        v.y = W0g[net * 256 + 1 * 64 + jj];
        v.z = W0g[net * 256 + 2 * 64 + jj];
        v.w = W0g[net * 256 + 3 * 64 + jj];
        w04[i] = v;
        b0s[i] = b0g[i];
        float2 t; t.x = b1g[i]; t.y = W2g[i];
        bw[i] = t;
    }
    if (tid < 4) b2s[tid] = b2g[tid];
    __syncthreads();

    // ---- per-row state ----
    const float S0b = S0g[b], Kb = Kg[b], Tb = Tg[b], rfv = rfg[0];
    const float dtv  = Tb * (1.0f / 32.0f);
    const float sqdt = sqrtf(dtv);
    const int   p    = pb * 128 + tid;
    const float4* z1p = (const float4*)(Z1g + p * NSTEPS);
    const float4* z2p = (const float4*)(Z2g + p * NSTEPS);
    float S = S0b, V = 0.2f;

    for (int jo = 0; jo < 8; ++jo) {
        const float4 z1v = z1p[jo];
        const float4 z2v = z2p[jo];
        #pragma unroll
        for (int ji = 0; ji < 4; ++ji) {
            const int j = jo * 4 + ji;
            const float z1 = (ji == 0) ? z1v.x : (ji == 1) ? z1v.y : (ji == 2) ? z1v.z : z1v.w;
            const float z2 = (ji == 0) ? z2v.x : (ji == 1) ? z2v.y : (ji == 2) ? z2v.z : z2v.w;
            const float tcol = dtv * (float)j;
            float fa, fb;
            run_phase(0, S, V, rfv, tcol, ab, tid, wid, lane, fa, fb);
            S = S * (1.0f + fa * dtv + fb * z1);
            run_phase(2, S, V, rfv, tcol, ab, tid, wid, lane, fa, fb);
            V = V * (1.0f + fa * dtv + fb * sqdt * z2);
        }
    }

    // ---- payoff + reduction ----
    float pay = (S - Kb < 0.0f) ? 0.0f : S;
    #pragma unroll
    for (int o = 16; o > 0; o >>= 1) pay += __shfl_xor_sync(0xFFFFFFFFu, pay, o);
    if (lane == 0) red[wid] = pay;
    __syncthreads();
    if (tid == 0)
        g_partial[blockIdx.x] = (red[0] + red[1]) + (red[2] + red[3]);
}

__global__ void nsde_finalize_kernel(const float* __restrict__ Tg,
                                     const float* __restrict__ rfg,
                                     float* __restrict__ out)
{
    int b = threadIdx.x;
    if (b < 64) {
        float s = (g_partial[b] + g_partial[64 + b]) + (g_partial[128 + b] + g_partial[192 + b]);
        out[b] = __expf(-rfg[0] * Tg[b]) * s * (1.0f / 512.0f);
    }
}

extern "C" void kernel_launch(void* const* d_in, const int* in_sizes, int n_in,
                              void* d_out, int out_size)
{
    const float* S0 = (const float*)d_in[0];
    const float* K  = (const float*)d_in[1];
    const float* T  = (const float*)d_in[2];
    const float* rf = (const float*)d_in[3];
    const float* Z1 = (const float*)d_in[4];
    const float* Z2 = (const float*)d_in[5];
    const float* W0 = (const float*)d_in[6];
    const float* b0 = (const float*)d_in[7];
    const float* W1 = (const float*)d_in[8];
    const float* b1 = (const float*)d_in[9];
    const float* W2 = (const float*)d_in[10];
    const float* b2 = (const float*)d_in[11];
    float* out = (float*)d_out;

    cudaFuncSetAttribute(nsde_main_kernel, cudaFuncAttributeMaxDynamicSharedMemorySize, SMEM_BYTES);
    nsde_main_kernel<<<256, 128, SMEM_BYTES>>>(S0, K, T, rf, Z1, Z2, W0, b0, W1, b1, W2, b2);
    nsde_finalize_kernel<<<1, 64>>>(T, rf, out);
}

// round 4
// speedup vs baseline: 2.1461x; 2.1461x over previous
#include <cuda_runtime.h>
#include <cuda_fp16.h>
#include <cstdint>

#define NSTEPS 32

// ---- smem layout (bytes) ----
#define OFF_W1T 0        // 4 nets x 64 n-rows x 72 halves (pitch 72) = 36864
#define OFF_A   36864    // 2 nets x 128 rows x 68 halves (pitch 68)  = 34816
#define OFF_W04 71680    // float4[256]
#define OFF_BW  75776    // float2[256] (b1, w2)
#define OFF_B0  77824    // float[256]
#define OFF_F   78848    // float[2][128]
#define OFF_B2  79872    // float[4]
#define OFF_RED 79888    // float[4]
#define SMEM_BYTES 79936

#define A_NET_HALVES   8704   // 128*68
#define A_PITCH_W      34     // words per A row
#define B_NET_WORDS    2304   // 64*36
#define B_PITCH_W      36

__device__ float g_partial[256];

// Single-instruction MUFU.TANH (sm_75+), max abs err ~1e-5
__device__ __forceinline__ float tanh_fast(float x) {
    float y;
    asm("tanh.approx.f32 %0, %1;" : "=f"(y) : "f"(x));
    return y;
}

__device__ __forceinline__ void mma16816(float& c0, float& c1, float& c2, float& c3,
                                         uint32_t a0, uint32_t a1, uint32_t a2, uint32_t a3,
                                         uint32_t b0, uint32_t b1) {
    asm volatile(
        "mma.sync.aligned.m16n8k16.row.col.f32.f16.f16.f32 "
        "{%0,%1,%2,%3},{%4,%5,%6,%7},{%8,%9},{%0,%1,%2,%3};"
        : "+f"(c0), "+f"(c1), "+f"(c2), "+f"(c3)
        : "r"(a0), "r"(a1), "r"(a2), "r"(a3), "r"(b0), "r"(b1));
}

// One phase: 2 MLPs (nets nb, nb+1) on shared input (S,V,rf,tcol) -> fA, fB per row.
// Entirely warp-local: each warp produces and consumes its own 32 rows.
__device__ __forceinline__ void run_phase(
    int nb, float S, float V, float rfv, float tcol,
    char* ab, int tid, int wid, int lane, float& fA, float& fB)
{
    const float4* w04 = (const float4*)(ab + OFF_W04);
    const float2* bw  = (const float2*)(ab + OFF_BW);
    const float*  b0s = (const float*)(ab + OFF_B0);
    const float*  b2s = (const float*)(ab + OFF_B2);
    uint32_t* Aw  = (uint32_t*)(ab + OFF_A);
    const uint32_t* Bw = (const uint32_t*)(ab + OFF_W1T);
    float* f_arr = (float*)(ab + OFF_F);

    const int g   = lane >> 2;   // group id (row within tiles)
    const int tig = lane & 3;    // thread in group
    const int wb  = wid * 32;    // warp's row base

    __syncwarp();   // WAR: prior phase's A/f reads done before overwrite

    // ---- layer 0: scalar fp32 -> h1 (fp16) into smem A, row = tid ----
    #pragma unroll
    for (int nl = 0; nl < 2; ++nl) {
        const int net = nb + nl;
        const float4* wp  = w04 + net * 64;
        const float*  b0p = b0s + net * 64;
        uint32_t* Arow = Aw + nl * (A_NET_HALVES / 2) + tid * A_PITCH_W;
        #pragma unroll 8
        for (int jj = 0; jj < 64; jj += 2) {
            float4 wa = wp[jj];
            float4 wbv = wp[jj + 1];
            float p0 = fmaf(wa.x, S, fmaf(wa.y, V, fmaf(wa.z, rfv, fmaf(wa.w, tcol, b0p[jj]))));
            float p1 = fmaf(wbv.x, S, fmaf(wbv.y, V, fmaf(wbv.z, rfv, fmaf(wbv.w, tcol, b0p[jj + 1]))));
            float h0 = tanh_fast(p0);
            float h1 = tanh_fast(p1);
            __half2 hh = __floats2half2_rn(h0, h1);
            Arow[jj >> 1] = *(const uint32_t*)&hh;
        }
    }
    __syncwarp();

    // ---- layer 1 (HMMA) + epilogue, per net ----
    #pragma unroll
    for (int nl = 0; nl < 2; ++nl) {
        const int net = nb + nl;

        // A fragments: 2 m-tiles x 4 k-tiles x 4 regs
        uint32_t afr[2][4][4];
        #pragma unroll
        for (int i = 0; i < 2; ++i) {
            const int row = wb + i * 16 + g;
            const uint32_t base = nl * (A_NET_HALVES / 2) + row * A_PITCH_W + tig;
            #pragma unroll
            for (int kt = 0; kt < 4; ++kt) {
                const uint32_t w = base + kt * 8;
                afr[i][kt][0] = Aw[w];
                afr[i][kt][1] = Aw[w + 8 * A_PITCH_W];
                afr[i][kt][2] = Aw[w + 4];
                afr[i][kt][3] = Aw[w + 4 + 8 * A_PITCH_W];
            }
        }

        float partial[4] = {0.f, 0.f, 0.f, 0.f};
        const uint32_t bbase = net * B_NET_WORDS + tig;

        #pragma unroll
        for (int j = 0; j < 8; ++j) {
            // B fragments for this n-tile (col n = j*8+g), all 4 k-tiles
            uint32_t bfr[4][2];
            const uint32_t bj = bbase + (j * 8 + g) * B_PITCH_W;
            #pragma unroll
            for (int kt = 0; kt < 4; ++kt) {
                bfr[kt][0] = Bw[bj + kt * 8];
                bfr[kt][1] = Bw[bj + kt * 8 + 4];
            }
            float c[2][4] = {{0.f,0.f,0.f,0.f},{0.f,0.f,0.f,0.f}};
            #pragma unroll
            for (int kt = 0; kt < 4; ++kt) {
                #pragma unroll
                for (int i = 0; i < 2; ++i)
                    mma16816(c[i][0], c[i][1], c[i][2], c[i][3],
                             afr[i][kt][0], afr[i][kt][1], afr[i][kt][2], afr[i][kt][3],
                             bfr[kt][0], bfr[kt][1]);
            }
            // epilogue for this n-tile: h2 = tanh(c + b1[n]); partial += h2*w2[n]
            const int n0 = j * 8 + tig * 2;
            float2 bw0 = bw[net * 64 + n0];
            float2 bw1 = bw[net * 64 + n0 + 1];
            #pragma unroll
            for (int i = 0; i < 2; ++i) {
                float h00 = tanh_fast(c[i][0] + bw0.x);
                float h01 = tanh_fast(c[i][1] + bw1.x);
                float h10 = tanh_fast(c[i][2] + bw0.x);
                float h11 = tanh_fast(c[i][3] + bw1.x);
                partial[2 * i]     = fmaf(h00, bw0.y, fmaf(h01, bw1.y, partial[2 * i]));
                partial[2 * i + 1] = fmaf(h10, bw0.y, fmaf(h11, bw1.y, partial[2 * i + 1]));
            }
        }
        // reduce across the 4 lanes of each g-group
        #pragma unroll
        for (int r = 0; r < 4; ++r) {
            partial[r] += __shfl_xor_sync(0xFFFFFFFFu, partial[r], 1);
            partial[r] += __shfl_xor_sync(0xFFFFFFFFu, partial[r], 2);
        }
        if (tig == 0) {
            const float bb = b2s[net];
            f_arr[nl * 128 + wb + g]      = partial[0] + bb;
            f_arr[nl * 128 + wb + g + 8]  = partial[1] + bb;
            f_arr[nl * 128 + wb + g + 16] = partial[2] + bb;
            f_arr[nl * 128 + wb + g + 24] = partial[3] + bb;
        }
    }
    __syncwarp();
    fA = f_arr[tid];
    fB = f_arr[128 + tid];
}

__global__ void __launch_bounds__(128)
nsde_main_kernel(const float* __restrict__ S0g, const float* __restrict__ Kg,
                 const float* __restrict__ Tg,  const float* __restrict__ rfg,
                 const float* __restrict__ Z1g, const float* __restrict__ Z2g,
                 const float* __restrict__ W0g, const float* __restrict__ b0g,
                 const float* __restrict__ W1g, const float* __restrict__ b1g,
                 const float* __restrict__ W2g, const float* __restrict__ b2g)
{
    extern __shared__ char ab[];
    const int tid  = threadIdx.x;
    const int wid  = tid >> 5;
    const int lane = tid & 31;
    const int b    = blockIdx.x & 63;   // option
    const int pb   = blockIdx.x >> 6;   // path block

    // ---- stage W1^T as fp16 [net][n][k], pitch 72 halves ----
    __half* W1T = (__half*)(ab + OFF_W1T);
    for (int i = tid; i < 4 * 64 * 64; i += 128) {
        const int net = i >> 12;
        const int k   = (i >> 6) & 63;
        const int n   = i & 63;
        W1T[net * 4608 + n * 72 + k] = __float2half_rn(W1g[i]);
    }
    float4* w04 = (float4*)(ab + OFF_W04);
    float2* bw  = (float2*)(ab + OFF_BW);
    float*  b0s = (float*)(ab + OFF_B0);
    float*  b2s = (float*)(ab + OFF_B2);
    float*  red = (float*)(ab + OFF_RED);
    for (int i = tid; i < 256; i += 128) {
        const int net = i >> 6, jj = i & 63;
        float4 v;
        v.x = W0g[net * 256 + 0 * 64 + jj];
        v.y = W0g[net * 256 + 1 * 64 + jj];
        v.z = W0g[net * 256 + 2 * 64 + jj];
        v.w = W0g[net * 256 + 3 * 64 + jj];
        w04[i] = v;
        b0s[i] = b0g[i];
        float2 t; t.x = b1g[i]; t.y = W2g[i];
        bw[i] = t;
    }
    if (tid < 4) b2s[tid] = b2g[tid];
    __syncthreads();

    // ---- per-row state ----
    const float S0b = S0g[b], Kb = Kg[b], Tb = Tg[b], rfv = rfg[0];
    const float dtv  = Tb * (1.0f / 32.0f);
    const float sqdt = sqrtf(dtv);
    const int   p    = pb * 128 + tid;
    const float4* z1p = (const float4*)(Z1g + p * NSTEPS);
    const float4* z2p = (const float4*)(Z2g + p * NSTEPS);
    float S = S0b, V = 0.2f;

    for (int jo = 0; jo < 8; ++jo) {
        const float4 z1v = z1p[jo];
        const float4 z2v = z2p[jo];
        #pragma unroll
        for (int ji = 0; ji < 4; ++ji) {
            const int j = jo * 4 + ji;
            const float z1 = (ji == 0) ? z1v.x : (ji == 1) ? z1v.y : (ji == 2) ? z1v.z : z1v.w;
            const float z2 = (ji == 0) ? z2v.x : (ji == 1) ? z2v.y : (ji == 2) ? z2v.z : z2v.w;
            const float tcol = dtv * (float)j;
            float fa, fb;
            run_phase(0, S, V, rfv, tcol, ab, tid, wid, lane, fa, fb);
            S = S * (1.0f + fa * dtv + fb * z1);
            run_phase(2, S, V, rfv, tcol, ab, tid, wid, lane, fa, fb);
            V = V * (1.0f + fa * dtv + fb * sqdt * z2);
        }
    }

    // ---- payoff + reduction ----
    float pay = (S - Kb < 0.0f) ? 0.0f : S;
    #pragma unroll
    for (int o = 16; o > 0; o >>= 1) pay += __shfl_xor_sync(0xFFFFFFFFu, pay, o);
    if (lane == 0) red[wid] = pay;
    __syncthreads();
    if (tid == 0)
        g_partial[blockIdx.x] = (red[0] + red[1]) + (red[2] + red[3]);
}

__global__ void nsde_finalize_kernel(const float* __restrict__ Tg,
                                     const float* __restrict__ rfg,
                                     float* __restrict__ out)
{
    int b = threadIdx.x;
    if (b < 64) {
        float s = (g_partial[b] + g_partial[64 + b]) + (g_partial[128 + b] + g_partial[192 + b]);
        out[b] = __expf(-rfg[0] * Tg[b]) * s * (1.0f / 512.0f);
    }
}

extern "C" void kernel_launch(void* const* d_in, const int* in_sizes, int n_in,
                              void* d_out, int out_size)
{
    const float* S0 = (const float*)d_in[0];
    const float* K  = (const float*)d_in[1];
    const float* T  = (const float*)d_in[2];
    const float* rf = (const float*)d_in[3];
    const float* Z1 = (const float*)d_in[4];
    const float* Z2 = (const float*)d_in[5];
    const float* W0 = (const float*)d_in[6];
    const float* b0 = (const float*)d_in[7];
    const float* W1 = (const float*)d_in[8];
    const float* b1 = (const float*)d_in[9];
    const float* W2 = (const float*)d_in[10];
    const float* b2 = (const float*)d_in[11];
    float* out = (float*)d_out;

    cudaFuncSetAttribute(nsde_main_kernel, cudaFuncAttributeMaxDynamicSharedMemorySize, SMEM_BYTES);
    nsde_main_kernel<<<256, 128, SMEM_BYTES>>>(S0, K, T, rf, Z1, Z2, W0, b0, W1, b1, W2, b2);
    nsde_finalize_kernel<<<1, 64>>>(T, rf, out);
}

// round 5
// speedup vs baseline: 2.4985x; 1.1642x over previous
#include <cuda_runtime.h>
#include <cuda_fp16.h>
#include <cstdint>

#define NSTEPS 32

// ---- smem layout (bytes) ----
#define OFF_W1T 0        // 4 nets x 64 n x 72 halves (pitch 72) = 36864
#define OFF_A   36864    // 2 nets x 128 rows x 68 halves (pitch 68) = 34816
#define OFF_W04 71680    // float4[256]
#define OFF_B0  75776    // float[256]
#define OFF_C0  76800    // float[256]   per-step uniform layer-0 term
#define OFF_BW  77824    // float2[256]  (b1, w2)
#define OFF_F   79872    // float[2][128]
#define OFF_B2  80896    // float[4]
#define OFF_RED 80912    // float[4]
#define SMEM_BYTES 80960

#define A_PITCH_W 34     // words per A row
#define A_NET_W   4352   // words per net (128*34)
#define B_PITCH_W 36
#define B_NET_W   2304

__device__ float g_partial[256];

__device__ __forceinline__ float tanh_fast(float x) {
    float y;
    asm("tanh.approx.f32 %0, %1;" : "=f"(y) : "f"(x));
    return y;
}

__device__ __forceinline__ void mma16816(float& c0, float& c1, float& c2, float& c3,
                                         uint32_t a0, uint32_t a1, uint32_t a2, uint32_t a3,
                                         uint32_t b0, uint32_t b1) {
    asm volatile(
        "mma.sync.aligned.m16n8k16.row.col.f32.f16.f16.f32 "
        "{%0,%1,%2,%3},{%4,%5,%6,%7},{%8,%9},{%0,%1,%2,%3};"
        : "+f"(c0), "+f"(c1), "+f"(c2), "+f"(c3)
        : "r"(a0), "r"(a1), "r"(a2), "r"(a3), "r"(b0), "r"(b1));
}

// One phase: 2 MLPs (nets nb, nb+1). 256 threads = 2 threads/row.
// Layer 0: thread (row, half) computes 32 of 64 hidden units per net.
// Layer 1: warp w owns m-tile rows [16w, 16w+16), both nets.
__device__ __forceinline__ void run_phase(
    int nb, float S, float V,
    char* ab, int tid, int wid, int lane, int row, int half,
    float& fA, float& fB)
{
    const float4* w04 = (const float4*)(ab + OFF_W04);
    const float*  c0s = (const float*)(ab + OFF_C0);
    const float2* bw  = (const float2*)(ab + OFF_BW);
    const float*  b2s = (const float*)(ab + OFF_B2);
    uint32_t* Aw  = (uint32_t*)(ab + OFF_A);
    const uint32_t* Bw = (const uint32_t*)(ab + OFF_W1T);
    float* f_arr = (float*)(ab + OFF_F);

    const int g   = lane >> 2;
    const int tig = lane & 3;
    const int jbase = half * 32;

    // ---- layer 0: 2 FMA + tanh per unit, h1 -> fp16 pairs into A ----
    #pragma unroll
    for (int nl = 0; nl < 2; ++nl) {
        const int net = nb + nl;
        const float4* wp  = w04 + net * 64 + jbase;
        const float*  cp  = c0s + net * 64 + jbase;
        uint32_t* Arow = Aw + nl * A_NET_W + row * A_PITCH_W + (jbase >> 1);
        #pragma unroll 8
        for (int jj = 0; jj < 32; jj += 2) {
            float4 wa = wp[jj];
            float4 wbv = wp[jj + 1];
            float p0 = fmaf(wa.x, S, fmaf(wa.y, V, cp[jj]));
            float p1 = fmaf(wbv.x, S, fmaf(wbv.y, V, cp[jj + 1]));
            float h0 = tanh_fast(p0);
            float h1 = tanh_fast(p1);
            __half2 hh = __floats2half2_rn(h0, h1);
            Arow[jj >> 1] = *(const uint32_t*)&hh;
        }
    }
    __syncthreads();

    // ---- layer 1 (HMMA, 1 m-tile per warp) + epilogue ----
    const int wb16 = wid * 16;
    #pragma unroll
    for (int nl = 0; nl < 2; ++nl) {
        const int net = nb + nl;

        uint32_t afr[4][4];
        {
            const uint32_t base = nl * A_NET_W + (wb16 + g) * A_PITCH_W + tig;
            #pragma unroll
            for (int kt = 0; kt < 4; ++kt) {
                const uint32_t w = base + kt * 8;
                afr[kt][0] = Aw[w];
                afr[kt][1] = Aw[w + 8 * A_PITCH_W];
                afr[kt][2] = Aw[w + 4];
                afr[kt][3] = Aw[w + 4 + 8 * A_PITCH_W];
            }
        }

        float partial0 = 0.f, partial1 = 0.f;
        const uint32_t bbase = net * B_NET_W + tig;

        #pragma unroll
        for (int j = 0; j < 8; ++j) {
            uint32_t bfr[4][2];
            const uint32_t bj = bbase + (j * 8 + g) * B_PITCH_W;
            #pragma unroll
            for (int kt = 0; kt < 4; ++kt) {
                bfr[kt][0] = Bw[bj + kt * 8];
                bfr[kt][1] = Bw[bj + kt * 8 + 4];
            }
            // two independent 2-deep accumulation chains
            float cA[4] = {0.f, 0.f, 0.f, 0.f};
            float cB[4] = {0.f, 0.f, 0.f, 0.f};
            mma16816(cA[0], cA[1], cA[2], cA[3],
                     afr[0][0], afr[0][1], afr[0][2], afr[0][3], bfr[0][0], bfr[0][1]);
            mma16816(cB[0], cB[1], cB[2], cB[3],
                     afr[2][0], afr[2][1], afr[2][2], afr[2][3], bfr[2][0], bfr[2][1]);
            mma16816(cA[0], cA[1], cA[2], cA[3],
                     afr[1][0], afr[1][1], afr[1][2], afr[1][3], bfr[1][0], bfr[1][1]);
            mma16816(cB[0], cB[1], cB[2], cB[3],
                     afr[3][0], afr[3][1], afr[3][2], afr[3][3], bfr[3][0], bfr[3][1]);

            const int n0 = j * 8 + tig * 2;
            float2 bw0 = bw[net * 64 + n0];
            float2 bw1 = bw[net * 64 + n0 + 1];
            float h00 = tanh_fast((cA[0] + cB[0]) + bw0.x);
            float h01 = tanh_fast((cA[1] + cB[1]) + bw1.x);
            float h10 = tanh_fast((cA[2] + cB[2]) + bw0.x);
            float h11 = tanh_fast((cA[3] + cB[3]) + bw1.x);
            partial0 = fmaf(h00, bw0.y, fmaf(h01, bw1.y, partial0));
            partial1 = fmaf(h10, bw0.y, fmaf(h11, bw1.y, partial1));
        }
        partial0 += __shfl_xor_sync(0xFFFFFFFFu, partial0, 1);
        partial0 += __shfl_xor_sync(0xFFFFFFFFu, partial0, 2);
        partial1 += __shfl_xor_sync(0xFFFFFFFFu, partial1, 1);
        partial1 += __shfl_xor_sync(0xFFFFFFFFu, partial1, 2);
        if (tig == 0) {
            const float bb = b2s[net];
            f_arr[nl * 128 + wb16 + g]     = partial0 + bb;
            f_arr[nl * 128 + wb16 + g + 8] = partial1 + bb;
        }
    }
    __syncthreads();
    fA = f_arr[row];
    fB = f_arr[128 + row];
}

__global__ void __launch_bounds__(256)
nsde_main_kernel(const float* __restrict__ S0g, const float* __restrict__ Kg,
                 const float* __restrict__ Tg,  const float* __restrict__ rfg,
                 const float* __restrict__ Z1g, const float* __restrict__ Z2g,
                 const float* __restrict__ W0g, const float* __restrict__ b0g,
                 const float* __restrict__ W1g, const float* __restrict__ b1g,
                 const float* __restrict__ W2g, const float* __restrict__ b2g)
{
    extern __shared__ char ab[];
    const int tid  = threadIdx.x;
    const int wid  = tid >> 5;
    const int lane = tid & 31;
    const int row  = tid & 127;
    const int half = tid >> 7;
    const int b    = blockIdx.x & 63;   // option
    const int pb   = blockIdx.x >> 6;   // path block

    // ---- stage weights ----
    __half* W1T = (__half*)(ab + OFF_W1T);
    for (int i = tid; i < 4 * 64 * 64; i += 256) {
        const int net = i >> 12;
        const int k   = (i >> 6) & 63;
        const int n   = i & 63;
        W1T[net * 4608 + n * 72 + k] = __float2half_rn(W1g[i]);
    }
    float4* w04 = (float4*)(ab + OFF_W04);
    float*  b0s = (float*)(ab + OFF_B0);
    float*  c0s = (float*)(ab + OFF_C0);
    float2* bw  = (float2*)(ab + OFF_BW);
    float*  b2s = (float*)(ab + OFF_B2);
    float*  red = (float*)(ab + OFF_RED);
    {
        const int i = tid;  // 256 threads, one each
        const int net = i >> 6, jj = i & 63;
        float4 v;
        v.x = W0g[net * 256 + 0 * 64 + jj];
        v.y = W0g[net * 256 + 1 * 64 + jj];
        v.z = W0g[net * 256 + 2 * 64 + jj];
        v.w = W0g[net * 256 + 3 * 64 + jj];
        w04[i] = v;
        b0s[i] = b0g[i];
        float2 t; t.x = b1g[i]; t.y = W2g[i];
        bw[i] = t;
    }
    if (tid < 4) b2s[tid] = b2g[tid];
    __syncthreads();

    // ---- per-row state (duplicated across the 2 half-threads of a row) ----
    const float S0b = S0g[b], Kb = Kg[b], Tb = Tg[b], rfv = rfg[0];
    const float dtv  = Tb * (1.0f / 32.0f);
    const float sqdt = sqrtf(dtv);
    const int   p    = pb * 128 + row;
    const float4* z1p = (const float4*)(Z1g + p * NSTEPS);
    const float4* z2p = (const float4*)(Z2g + p * NSTEPS);
    float S = S0b, V = 0.2f;
    const float4 myw = w04[tid];
    const float myb0 = b0s[tid];

    for (int jo = 0; jo < 8; ++jo) {
        const float4 z1v = z1p[jo];
        const float4 z2v = z2p[jo];
        #pragma unroll
        for (int ji = 0; ji < 4; ++ji) {
            const int j = jo * 4 + ji;
            const float z1 = (ji == 0) ? z1v.x : (ji == 1) ? z1v.y : (ji == 2) ? z1v.z : z1v.w;
            const float z2 = (ji == 0) ? z2v.x : (ji == 1) ? z2v.y : (ji == 2) ? z2v.z : z2v.w;
            const float tcol = dtv * (float)j;
            // per-step uniform layer-0 term: c0 = w.z*rf + w.w*tcol + b0
            c0s[tid] = fmaf(myw.z, rfv, fmaf(myw.w, tcol, myb0));
            __syncthreads();
            float fa, fb;
            run_phase(0, S, V, ab, tid, wid, lane, row, half, fa, fb);
            S = S * (1.0f + fa * dtv + fb * z1);
            run_phase(2, S, V, ab, tid, wid, lane, row, half, fa, fb);
            V = V * (1.0f + fa * dtv + fb * sqdt * z2);
        }
    }

    // ---- payoff + reduction (half 0 only: warps 0..3, full warps) ----
    if (tid < 128) {
        float pay = (S - Kb < 0.0f) ? 0.0f : S;
        #pragma unroll
        for (int o = 16; o > 0; o >>= 1) pay += __shfl_xor_sync(0xFFFFFFFFu, pay, o);
        if (lane == 0) red[wid] = pay;
    }
    __syncthreads();
    if (tid == 0)
        g_partial[blockIdx.x] = (red[0] + red[1]) + (red[2] + red[3]);
}

__global__ void nsde_finalize_kernel(const float* __restrict__ Tg,
                                     const float* __restrict__ rfg,
                                     float* __restrict__ out)
{
    int b = threadIdx.x;
    if (b < 64) {
        float s = (g_partial[b] + g_partial[64 + b]) + (g_partial[128 + b] + g_partial[192 + b]);
        out[b] = __expf(-rfg[0] * Tg[b]) * s * (1.0f / 512.0f);
    }
}

extern "C" void kernel_launch(void* const* d_in, const int* in_sizes, int n_in,
                              void* d_out, int out_size)
{
    const float* S0 = (const float*)d_in[0];
    const float* K  = (const float*)d_in[1];
    const float* T  = (const float*)d_in[2];
    const float* rf = (const float*)d_in[3];
    const float* Z1 = (const float*)d_in[4];
    const float* Z2 = (const float*)d_in[5];
    const float* W0 = (const float*)d_in[6];
    const float* b0 = (const float*)d_in[7];
    const float* W1 = (const float*)d_in[8];
    const float* b1 = (const float*)d_in[9];
    const float* W2 = (const float*)d_in[10];
    const float* b2 = (const float*)d_in[11];
    float* out = (float*)d_out;

    cudaFuncSetAttribute(nsde_main_kernel, cudaFuncAttributeMaxDynamicSharedMemorySize, SMEM_BYTES);
    nsde_main_kernel<<<256, 256, SMEM_BYTES>>>(S0, K, T, rf, Z1, Z2, W0, b0, W1, b1, W2, b2);
    nsde_finalize_kernel<<<1, 64>>>(T, rf, out);
}